// round 3
// baseline (speedup 1.0000x reference)
#include <cuda_runtime.h>
#include <cuda_bf16.h>
#include <math.h>
#include <stdint.h>

#define TT 8192
#define DD 1024
#define HH 4096
#define EE 8

#define BM 128
#define BN 128
#define NSTG 3
#define STG_BYTES 40960   // 4 planes x 128 rows x 80B

typedef __nv_bfloat16 bf16;

// ---------------- scratch (static device globals; no allocations) ----------
__device__ int   g_count[EE];
__device__ int   g_cursor[EE];
__device__ int   g_offset[EE];
__device__ int   g_sel[TT * 2];
__device__ float g_wt[TT * 2];
__device__ int   g_btok[TT * 2];
__device__ float g_bw[TT * 2];
__device__ int   g_pos[TT * 2];

__device__ bf16  g_xhi[(size_t)TT * DD];
__device__ bf16  g_xlo[(size_t)TT * DD];
__device__ bf16  g_w1hi[(size_t)EE * HH * DD];  // [E][H][D] transposed, K-major rows
__device__ bf16  g_w1lo[(size_t)EE * HH * DD];
__device__ bf16  g_w2hi[(size_t)EE * DD * HH];  // [E][D][H]
__device__ bf16  g_w2lo[(size_t)EE * DD * HH];
__device__ bf16  g_hhi[(size_t)TT * 2 * HH];
__device__ bf16  g_hlo[(size_t)TT * 2 * HH];
__device__ float g_yb[(size_t)TT * 2 * DD];

// ---------------- PTX helpers ----------------------------------------------
__device__ __forceinline__ uint32_t s2u(const void* p) {
    uint32_t a;
    asm("{ .reg .u64 t; cvta.to.shared.u64 t, %1; cvt.u32.u64 %0, t; }" : "=r"(a) : "l"(p));
    return a;
}
__device__ __forceinline__ void cp16(uint32_t s, const void* g) {
    asm volatile("cp.async.cg.shared.global [%0], [%1], 16;" :: "r"(s), "l"(g) : "memory");
}
__device__ __forceinline__ void cp_commit() {
    asm volatile("cp.async.commit_group;" ::: "memory");
}
__device__ __forceinline__ void cp_wait1() {
    asm volatile("cp.async.wait_group 1;" ::: "memory");
}
__device__ __forceinline__ void ldsm4(uint32_t* r, uint32_t a) {
    asm volatile("ldmatrix.sync.aligned.m8n8.x4.shared.b16 {%0,%1,%2,%3}, [%4];"
                 : "=r"(r[0]), "=r"(r[1]), "=r"(r[2]), "=r"(r[3]) : "r"(a));
}
__device__ __forceinline__ void mma_bf16(float* d, const uint32_t* a, const uint32_t* b) {
    asm volatile(
        "mma.sync.aligned.m16n8k16.row.col.f32.bf16.bf16.f32 "
        "{%0,%1,%2,%3}, {%4,%5,%6,%7}, {%8,%9}, {%0,%1,%2,%3};"
        : "+f"(d[0]), "+f"(d[1]), "+f"(d[2]), "+f"(d[3])
        : "r"(a[0]), "r"(a[1]), "r"(a[2]), "r"(a[3]), "r"(b[0]), "r"(b[1]));
}

// ---------------- small kernels ---------------------------------------------
__global__ void k_zero() { if (threadIdx.x < EE) g_count[threadIdx.x] = 0; }

__global__ void k_xsplit(const float* __restrict__ x) {
    size_t i = ((size_t)blockIdx.x * blockDim.x + threadIdx.x) * 4;
    float4 v = *(const float4*)(x + i);
    float vv[4] = {v.x, v.y, v.z, v.w};
#pragma unroll
    for (int q = 0; q < 4; q++) {
        bf16 hi = __float2bfloat16(vv[q]);
        g_xhi[i + q] = hi;
        g_xlo[i + q] = __float2bfloat16(vv[q] - __bfloat162float(hi));
    }
}

// W[e][r][c] fp32 -> Whi/Wlo[e][c][r] bf16 (transpose + split)
__global__ void k_wsplit(const float* __restrict__ W, bf16* __restrict__ Whi,
                         bf16* __restrict__ Wlo, int R, int C) {
    __shared__ float tile[32][33];
    int e = blockIdx.z;
    int c0 = blockIdx.x * 32, r0 = blockIdx.y * 32;
    const float* We = W + (size_t)e * R * C;
#pragma unroll
    for (int j = 0; j < 32; j += 8)
        tile[threadIdx.y + j][threadIdx.x] =
            We[(size_t)(r0 + threadIdx.y + j) * C + c0 + threadIdx.x];
    __syncthreads();
#pragma unroll
    for (int j = 0; j < 32; j += 8) {
        int c = c0 + threadIdx.y + j;
        int r = r0 + threadIdx.x;
        float v = tile[threadIdx.x][threadIdx.y + j];
        bf16 hi = __float2bfloat16(v);
        size_t o = ((size_t)e * C + c) * R + r;
        Whi[o] = hi;
        Wlo[o] = __float2bfloat16(v - __bfloat162float(hi));
    }
}

__global__ void k_router(const float* __restrict__ x, const float* __restrict__ Wg,
                         float* __restrict__ out_logits) {
    int t = blockIdx.x * (blockDim.x >> 5) + (threadIdx.x >> 5);
    int lane = threadIdx.x & 31;
    if (t >= TT) return;
    const float* xr = x + (size_t)t * DD;
    float acc[EE];
#pragma unroll
    for (int e = 0; e < EE; e++) acc[e] = 0.f;
    for (int j = lane; j < DD; j += 32) {
        float xv = xr[j];
#pragma unroll
        for (int e = 0; e < EE; e++) acc[e] = fmaf(xv, Wg[e * DD + j], acc[e]);
    }
#pragma unroll
    for (int e = 0; e < EE; e++) {
#pragma unroll
        for (int o = 16; o > 0; o >>= 1) acc[e] += __shfl_xor_sync(0xffffffffu, acc[e], o);
    }
    if (lane == 0) {
        float mx = acc[0];
#pragma unroll
        for (int e = 1; e < EE; e++) mx = fmaxf(mx, acc[e]);
        float p[EE]; float den = 0.f;
#pragma unroll
        for (int e = 0; e < EE; e++) { p[e] = expf(acc[e] - mx); den += p[e]; }
        float inv = 1.f / den;
#pragma unroll
        for (int e = 0; e < EE; e++) p[e] *= inv;
        int i0 = 0;
#pragma unroll
        for (int e = 1; e < EE; e++) if (p[e] > p[i0]) i0 = e;
        int i1 = (i0 == 0) ? 1 : 0;
#pragma unroll
        for (int e = 0; e < EE; e++) if (e != i0 && p[e] > p[i1]) i1 = e;
        float w0 = p[i0], w1 = p[i1];
        float s = 1.f / (w0 + w1);
        g_sel[t * 2] = i0; g_sel[t * 2 + 1] = i1;
        g_wt[t * 2] = w0 * s; g_wt[t * 2 + 1] = w1 * s;
        atomicAdd(&g_count[i0], 1);
        atomicAdd(&g_count[i1], 1);
#pragma unroll
        for (int e = 0; e < EE; e++) out_logits[(size_t)t * EE + e] = acc[e];
    }
}

__global__ void k_offsets() {
    int o = 0;
    for (int e = 0; e < EE; e++) { g_offset[e] = o; g_cursor[e] = o; o += g_count[e]; }
}

__global__ void k_scatter() {
    int t = blockIdx.x * blockDim.x + threadIdx.x;
    if (t >= TT) return;
#pragma unroll
    for (int k = 0; k < 2; k++) {
        int e = g_sel[t * 2 + k];
        int idx = atomicAdd(&g_cursor[e], 1);
        g_btok[idx] = t;
        g_bw[idx] = g_wt[t * 2 + k];
        g_pos[t * 2 + k] = idx;
    }
}

// ---------------- grouped split-bf16 HMMA GEMM -------------------------------
// UP:  g_h{hi,lo}[bucket] = split( gelu(x[gather] @ W1t[e]^T) * gate )
// !UP: g_yb[bucket]       = h[bucket] @ W2t[e]^T
// Stage layout (per stage, 40960B): Ahi @0, Alo @10240, Bhi @20480, Blo @30720
// Row stride 80B (32 bf16 + 8 pad) -> conflict-free ldmatrix (5 coprime 8).
template<int KD, int ND, bool UP>
__global__ __launch_bounds__(256, 1)
void k_mma(const bf16* __restrict__ Whi, const bf16* __restrict__ Wlo) {
    const int e   = blockIdx.z;
    const int cnt = g_count[e];
    const int rt  = blockIdx.y;
    if (rt * BM >= cnt) return;
    const int off = g_offset[e];
    const int n0  = blockIdx.x * BN;
    const int tid = threadIdx.x;
    const int lane = tid & 31, wid = tid >> 5;
    const int wm = wid & 3, wn = wid >> 2;

    extern __shared__ char smem[];
    const uint32_t sb = s2u(smem);
    __shared__ int stok[BM];

    if (tid < BM) {
        int gr = rt * BM + tid;
        if (gr >= cnt) gr = cnt - 1;
        stok[tid] = UP ? g_btok[off + gr] : (off + gr);
    }
    __syncthreads();

    const bf16* Ahi = UP ? g_xhi : g_hhi;
    const bf16* Alo = UP ? g_xlo : g_hlo;
    const int NK = KD / 32;

    auto load_stage = [&](int ls) {
        if (ls < NK) {
            const int kt = ls * 32;
            const uint32_t st = sb + (ls % NSTG) * STG_BYTES;
#pragma unroll
            for (int it = 0; it < 8; it++) {
                int id = tid + it * 256;
                int plane = id >> 9;
                int r = (id >> 2) & 127;
                int c = id & 3;
                uint32_t so = st + plane * 10240 + r * 80 + c * 16;
                const bf16* gp;
                if (plane == 0)      gp = Ahi + (size_t)stok[r] * KD + kt + c * 8;
                else if (plane == 1) gp = Alo + (size_t)stok[r] * KD + kt + c * 8;
                else if (plane == 2) gp = Whi + ((size_t)e * ND + n0 + r) * KD + kt + c * 8;
                else                 gp = Wlo + ((size_t)e * ND + n0 + r) * KD + kt + c * 8;
                cp16(so, gp);
            }
        }
        cp_commit();
    };

    float acc[2][8][4];
#pragma unroll
    for (int i = 0; i < 2; i++)
#pragma unroll
        for (int j = 0; j < 8; j++)
#pragma unroll
            for (int q = 0; q < 4; q++) acc[i][j][q] = 0.f;

    load_stage(0);
    load_stage(1);

    for (int s = 0; s < NK; s++) {
        cp_wait1();
        __syncthreads();
        load_stage(s + 2);
        const uint32_t st = sb + (s % NSTG) * STG_BYTES;
#pragma unroll
        for (int k16 = 0; k16 < 2; k16++) {
            uint32_t af[2][2][4];   // [plane][mtile][4]
            uint32_t bfr[2][4][4];  // [plane][btile][4]
#pragma unroll
            for (int mt = 0; mt < 2; mt++) {
                int row = wm * 32 + mt * 16 + (lane & 15);
                uint32_t a = st + row * 80 + (k16 * 16 + (lane >> 4) * 8) * 2;
                ldsm4(af[0][mt], a);
                ldsm4(af[1][mt], a + 10240);
            }
#pragma unroll
            for (int bt = 0; bt < 4; bt++) {
                int n = wn * 64 + bt * 16 + (lane & 7) + ((lane & 16) >> 1);
                uint32_t b = st + 20480 + n * 80 + (k16 * 16 + ((lane >> 3) & 1) * 8) * 2;
                ldsm4(bfr[0][bt], b);
                ldsm4(bfr[1][bt], b + 10240);
            }
#pragma unroll
            for (int mt = 0; mt < 2; mt++)
#pragma unroll
                for (int nt = 0; nt < 8; nt++) {
                    const uint32_t* bh = &bfr[0][nt >> 1][(nt & 1) * 2];
                    const uint32_t* bl = &bfr[1][nt >> 1][(nt & 1) * 2];
                    mma_bf16(acc[mt][nt], af[0][mt], bh);   // hi*hi
                    mma_bf16(acc[mt][nt], af[0][mt], bl);   // hi*lo
                    mma_bf16(acc[mt][nt], af[1][mt], bh);   // lo*hi
                }
        }
    }

    // ---------------- epilogue ----------------
#pragma unroll
    for (int mt = 0; mt < 2; mt++) {
        const int rbase = wm * 32 + mt * 16 + (lane >> 2);
#pragma unroll
        for (int half = 0; half < 2; half++) {
            const int rl = rbase + half * 8;
            const int gr = rt * BM + rl;
            if (gr >= cnt) continue;
            const size_t base = (size_t)(off + gr) * ND + n0 + wn * 64 + (lane & 3) * 2;
            if (UP) {
                const float gate = g_bw[off + gr];
#pragma unroll
                for (int nt = 0; nt < 8; nt++) {
                    float z0 = acc[mt][nt][half * 2 + 0];
                    float z1 = acc[mt][nt][half * 2 + 1];
                    z0 = 0.5f * z0 * (1.f + erff(z0 * 0.70710678118654752f)) * gate;
                    z1 = 0.5f * z1 * (1.f + erff(z1 * 0.70710678118654752f)) * gate;
                    bf16 h0 = __float2bfloat16(z0);
                    bf16 h1 = __float2bfloat16(z1);
                    bf16 l0 = __float2bfloat16(z0 - __bfloat162float(h0));
                    bf16 l1 = __float2bfloat16(z1 - __bfloat162float(h1));
                    union { bf16 b[2]; uint32_t u; } ph, pl;
                    ph.b[0] = h0; ph.b[1] = h1;
                    pl.b[0] = l0; pl.b[1] = l1;
                    *(uint32_t*)(g_hhi + base + nt * 8) = ph.u;
                    *(uint32_t*)(g_hlo + base + nt * 8) = pl.u;
                }
            } else {
#pragma unroll
                for (int nt = 0; nt < 8; nt++) {
                    float2 v = make_float2(acc[mt][nt][half * 2 + 0],
                                           acc[mt][nt][half * 2 + 1]);
                    *(float2*)(g_yb + base + nt * 8) = v;
                }
            }
        }
    }
}

__global__ void k_combine(float* __restrict__ y) {
    int i = blockIdx.x * blockDim.x + threadIdx.x;
    const int nv = TT * DD / 4;
    if (i >= nv) return;
    int t = i / (DD / 4);
    int d4 = i % (DD / 4);
    int p0 = g_pos[2 * t], p1 = g_pos[2 * t + 1];
    float4 a = ((const float4*)(g_yb + (size_t)p0 * DD))[d4];
    float4 b = ((const float4*)(g_yb + (size_t)p1 * DD))[d4];
    ((float4*)(y + (size_t)t * DD))[d4] = make_float4(a.x + b.x, a.y + b.y, a.z + b.z, a.w + b.w);
}

// ---------------- launch -----------------------------------------------------
extern "C" void kernel_launch(void* const* d_in, const int* in_sizes, int n_in,
                              void* d_out, int out_size) {
    const float* x  = (const float*)d_in[0];
    const float* Wg = (const float*)d_in[1];
    const float* W1 = (const float*)d_in[2];
    const float* W2 = (const float*)d_in[3];
    float* out = (float*)d_out;
    float* y = out;
    float* logits = out + (size_t)TT * DD;

    const int DSM = NSTG * STG_BYTES;
    cudaFuncSetAttribute(k_mma<DD, HH, true>,  cudaFuncAttributeMaxDynamicSharedMemorySize, DSM);
    cudaFuncSetAttribute(k_mma<HH, DD, false>, cudaFuncAttributeMaxDynamicSharedMemorySize, DSM);

    k_zero<<<1, 32>>>();
    k_xsplit<<<TT * DD / (256 * 4), 256>>>(x);
    {
        dim3 g1(HH / 32, DD / 32, EE);
        k_wsplit<<<g1, dim3(32, 8)>>>(W1, g_w1hi, g_w1lo, DD, HH);
        dim3 g2(DD / 32, HH / 32, EE);
        k_wsplit<<<g2, dim3(32, 8)>>>(W2, g_w2hi, g_w2lo, HH, DD);
    }
    k_router<<<TT / 8, 256>>>(x, Wg, logits);
    k_offsets<<<1, 1>>>();
    k_scatter<<<TT / 256, 256>>>();

    dim3 gup(HH / BN, TT / BM, EE);
    k_mma<DD, HH, true><<<gup, 256, DSM>>>(g_w1hi, g_w1lo);

    dim3 gdn(DD / BN, TT / BM, EE);
    k_mma<HH, DD, false><<<gdn, 256, DSM>>>(g_w2hi, g_w2lo);

    k_combine<<<(TT * DD / 4 + 255) / 256, 256>>>(y);
}

// round 4
// speedup vs baseline: 9.1881x; 9.1881x over previous
#include <cuda_runtime.h>
#include <math.h>
#include <stdint.h>

// Problem dims (fixed by the dataset)
#define TT 8192
#define DD 1024
#define HH 4096
#define EE 8

// GEMM tiling
#define BM 128
#define BN 128
#define BK 16
#define TM 8
#define TN 8

// ---------------- scratch (static device globals; no allocations) ----------
__device__ int   g_count[EE];
__device__ int   g_cursor[EE];
__device__ int   g_offset[EE];
__device__ int   g_sel[TT * 2];
__device__ float g_wt[TT * 2];
__device__ int   g_btok[TT * 2];               // bucket: token ids grouped by expert
__device__ float g_bw[TT * 2];                 // bucket: renormalized gate weights
__device__ int   g_pos[TT * 2];                // (token,slot) -> bucket index
__device__ float g_h[(size_t)TT * 2 * HH];     // grouped gated activations
__device__ float g_yb[(size_t)TT * 2 * DD];    // grouped partial outputs

// ---------------- f32x2 helpers ----------------------------------------------
__device__ __forceinline__ void fma2(unsigned long long& d, unsigned long long a,
                                     unsigned long long b) {
    asm("fma.rn.f32x2 %0, %1, %2, %0;" : "+l"(d) : "l"(a), "l"(b));
}
__device__ __forceinline__ unsigned long long splat2(float a) {
    unsigned long long d;
    asm("mov.b64 %0, {%1, %1};" : "=l"(d) : "f"(a));
    return d;
}
__device__ __forceinline__ float2 unpack2(unsigned long long v) {
    float2 r;
    asm("mov.b64 {%0, %1}, %2;" : "=f"(r.x), "=f"(r.y) : "l"(v));
    return r;
}

// ---------------- kernels ---------------------------------------------------

__global__ void k_zero() {
    if (threadIdx.x < EE) g_count[threadIdx.x] = 0;
}

// Router: logits = x @ Wg^T, softmax, top-2, renormalize. One warp per token.
__global__ void k_router(const float* __restrict__ x, const float* __restrict__ Wg,
                         float* __restrict__ out_logits) {
    int t = blockIdx.x * (blockDim.x >> 5) + (threadIdx.x >> 5);
    int lane = threadIdx.x & 31;
    if (t >= TT) return;
    const float* xr = x + (size_t)t * DD;

    float acc[EE];
#pragma unroll
    for (int e = 0; e < EE; e++) acc[e] = 0.f;
    for (int j = lane; j < DD; j += 32) {
        float xv = xr[j];
#pragma unroll
        for (int e = 0; e < EE; e++) acc[e] = fmaf(xv, Wg[e * DD + j], acc[e]);
    }
#pragma unroll
    for (int e = 0; e < EE; e++) {
#pragma unroll
        for (int o = 16; o > 0; o >>= 1) acc[e] += __shfl_xor_sync(0xffffffffu, acc[e], o);
    }
    if (lane == 0) {
        float mx = acc[0];
#pragma unroll
        for (int e = 1; e < EE; e++) mx = fmaxf(mx, acc[e]);
        float p[EE];
        float den = 0.f;
#pragma unroll
        for (int e = 0; e < EE; e++) { p[e] = expf(acc[e] - mx); den += p[e]; }
        float inv = 1.f / den;
#pragma unroll
        for (int e = 0; e < EE; e++) p[e] *= inv;

        int i0 = 0;
#pragma unroll
        for (int e = 1; e < EE; e++) if (p[e] > p[i0]) i0 = e;
        int i1 = (i0 == 0) ? 1 : 0;
#pragma unroll
        for (int e = 0; e < EE; e++) if (e != i0 && p[e] > p[i1]) i1 = e;

        float w0 = p[i0], w1 = p[i1];
        float s = 1.f / (w0 + w1);
        w0 *= s; w1 *= s;

        g_sel[t * 2] = i0; g_sel[t * 2 + 1] = i1;
        g_wt[t * 2] = w0;  g_wt[t * 2 + 1] = w1;
        atomicAdd(&g_count[i0], 1);
        atomicAdd(&g_count[i1], 1);
#pragma unroll
        for (int e = 0; e < EE; e++) out_logits[(size_t)t * EE + e] = acc[e];
    }
}

__global__ void k_offsets() {
    int o = 0;
    for (int e = 0; e < EE; e++) { g_offset[e] = o; g_cursor[e] = o; o += g_count[e]; }
}

__global__ void k_scatter() {
    int t = blockIdx.x * blockDim.x + threadIdx.x;
    if (t >= TT) return;
#pragma unroll
    for (int k = 0; k < 2; k++) {
        int e = g_sel[t * 2 + k];
        int idx = atomicAdd(&g_cursor[e], 1);
        g_btok[idx] = t;
        g_bw[idx] = g_wt[t * 2 + k];
        g_pos[t * 2 + k] = idx;
    }
}

// Grouped GEMM (fp32, packed f32x2 FMA).
// UP=true:  g_h[idx]  = gelu(x[gather] @ W1[e]) * gate
// UP=false: g_yb[idx] = g_h[idx] @ W2[e]
template<int KD, int ND, bool UP>
__global__ __launch_bounds__(256, 2)
void k_ggemm(const float* __restrict__ Ag, const float* __restrict__ Bg) {
    const int e = blockIdx.z;
    const int cnt = g_count[e];
    const int rt = blockIdx.y;
    if (rt * BM >= cnt) return;
    const int off = g_offset[e];
    const int n0 = blockIdx.x * BN;
    const int tid = threadIdx.x;

    __shared__ float As[2][BK][BM + 4];
    __shared__ float Bs[2][BK][BN];
    __shared__ int   stok[BM];

    if (UP) {
        if (tid < BM) {
            int gr = rt * BM + tid;
            stok[tid] = g_btok[off + ((gr < cnt) ? gr : (cnt - 1))];
        }
    }
    __syncthreads();

    const float* Bexp = Bg + (size_t)e * KD * ND;

    // Per-thread load slots.
    // A: 2 slots, slot i covers row (tid>>2)+64*i, k-quad tid&3 (float4).
    // B: 2 slots, slot i covers kk=(tid+256i)>>5, n-quad tid&31 (float4).
    const int ar0 = tid >> 2, ak4 = tid & 3;
    const int ar1 = ar0 + 64;
    const float* a_src0;
    const float* a_src1;
    if (UP) {
        a_src0 = Ag + (size_t)stok[ar0] * KD + ak4 * 4;
        a_src1 = Ag + (size_t)stok[ar1] * KD + ak4 * 4;
    } else {
        int g0 = rt * BM + ar0; if (g0 >= cnt) g0 = cnt - 1;
        int g1 = rt * BM + ar1; if (g1 >= cnt) g1 = cnt - 1;
        a_src0 = g_h + (size_t)(off + g0) * KD + ak4 * 4;
        a_src1 = g_h + (size_t)(off + g1) * KD + ak4 * 4;
    }
    const int bkk0 = tid >> 5, bn4 = tid & 31;
    const float* b_src0 = Bexp + (size_t)bkk0 * ND + n0 + bn4 * 4;
    const float* b_src1 = b_src0 + (size_t)8 * ND;

    float4 pa0, pa1, pb0, pb1;

    auto fetch = [&](int kt) {
        pa0 = *(const float4*)(a_src0 + kt);
        pa1 = *(const float4*)(a_src1 + kt);
        pb0 = *(const float4*)(b_src0 + (size_t)kt * ND);
        pb1 = *(const float4*)(b_src1 + (size_t)kt * ND);
    };
    auto store = [&](int buf) {
        As[buf][ak4 * 4 + 0][ar0] = pa0.x;
        As[buf][ak4 * 4 + 1][ar0] = pa0.y;
        As[buf][ak4 * 4 + 2][ar0] = pa0.z;
        As[buf][ak4 * 4 + 3][ar0] = pa0.w;
        As[buf][ak4 * 4 + 0][ar1] = pa1.x;
        As[buf][ak4 * 4 + 1][ar1] = pa1.y;
        As[buf][ak4 * 4 + 2][ar1] = pa1.z;
        As[buf][ak4 * 4 + 3][ar1] = pa1.w;
        *(float4*)&Bs[buf][bkk0][bn4 * 4]     = pb0;
        *(float4*)&Bs[buf][bkk0 + 8][bn4 * 4] = pb1;
    };

    unsigned long long acc2[TM][TN / 2];
#pragma unroll
    for (int i = 0; i < TM; i++)
#pragma unroll
        for (int j = 0; j < TN / 2; j++) acc2[i][j] = 0ull;

    fetch(0);
    store(0);
    __syncthreads();

    const int tx = tid & 15, ty = tid >> 4;
    const int NK = KD / BK;
    for (int kt = 0; kt < NK; kt++) {
        const int cur = kt & 1;
        if (kt + 1 < NK) fetch((kt + 1) * BK);
#pragma unroll
        for (int k = 0; k < BK; k++) {
            float4 a03 = *(const float4*)&As[cur][k][ty * TM];
            float4 a47 = *(const float4*)&As[cur][k][ty * TM + 4];
            ulonglong2 b01 = *(const ulonglong2*)&Bs[cur][k][tx * TN];
            ulonglong2 b23 = *(const ulonglong2*)&Bs[cur][k][tx * TN + 4];
            unsigned long long bp0 = b01.x, bp1 = b01.y, bp2 = b23.x, bp3 = b23.y;
            float av[TM] = {a03.x, a03.y, a03.z, a03.w, a47.x, a47.y, a47.z, a47.w};
#pragma unroll
            for (int i = 0; i < TM; i++) {
                unsigned long long asp = splat2(av[i]);
                fma2(acc2[i][0], asp, bp0);
                fma2(acc2[i][1], asp, bp1);
                fma2(acc2[i][2], asp, bp2);
                fma2(acc2[i][3], asp, bp3);
            }
        }
        if (kt + 1 < NK) store(cur ^ 1);
        __syncthreads();
    }

    // epilogue
#pragma unroll
    for (int i = 0; i < TM; i++) {
        int gr = rt * BM + ty * TM + i;
        if (gr >= cnt) continue;
        float* crow;
        float gate = 1.f;
        if (UP) {
            gate = g_bw[off + gr];
            crow = g_h + (size_t)(off + gr) * ND;
        } else {
            crow = g_yb + (size_t)(off + gr) * ND;
        }
#pragma unroll
        for (int j2 = 0; j2 < TN / 2; j2 += 2) {
            float2 v0 = unpack2(acc2[i][j2]);
            float2 v1 = unpack2(acc2[i][j2 + 1]);
            float vv[4] = {v0.x, v0.y, v1.x, v1.y};
            if (UP) {
#pragma unroll
                for (int q = 0; q < 4; q++) {
                    float z = vv[q];
                    vv[q] = 0.5f * z * (1.f + erff(z * 0.70710678118654752f)) * gate;
                }
            }
            *(float4*)(crow + n0 + tx * TN + j2 * 2) = make_float4(vv[0], vv[1], vv[2], vv[3]);
        }
    }
}

__global__ void k_combine(float* __restrict__ y) {
    int i = blockIdx.x * blockDim.x + threadIdx.x;
    const int nv = TT * DD / 4;
    if (i >= nv) return;
    int t = i / (DD / 4);
    int d4 = i % (DD / 4);
    int p0 = g_pos[2 * t], p1 = g_pos[2 * t + 1];
    float4 a = ((const float4*)(g_yb + (size_t)p0 * DD))[d4];
    float4 b = ((const float4*)(g_yb + (size_t)p1 * DD))[d4];
    float4 o = make_float4(a.x + b.x, a.y + b.y, a.z + b.z, a.w + b.w);
    ((float4*)(y + (size_t)t * DD))[d4] = o;
}

// ---------------- launch -----------------------------------------------------

extern "C" void kernel_launch(void* const* d_in, const int* in_sizes, int n_in,
                              void* d_out, int out_size) {
    const float* x  = (const float*)d_in[0];
    const float* Wg = (const float*)d_in[1];
    const float* W1 = (const float*)d_in[2];
    const float* W2 = (const float*)d_in[3];
    float* out = (float*)d_out;
    float* y = out;                                 // [T, D]
    float* logits = out + (size_t)TT * DD;          // [T, E]

    k_zero<<<1, 32>>>();
    k_router<<<TT / 8, 256>>>(x, Wg, logits);
    k_offsets<<<1, 1>>>();
    k_scatter<<<TT / 256, 256>>>();

    dim3 gup(HH / BN, TT / BM, EE);
    k_ggemm<DD, HH, true><<<gup, 256>>>(x, W1);

    dim3 gdn(DD / BN, TT / BM, EE);
    k_ggemm<HH, DD, false><<<gdn, 256>>>(nullptr, W2);

    k_combine<<<(TT * DD / 4 + 255) / 256, 256>>>(y);
}

// round 6
// speedup vs baseline: 10.2620x; 1.1169x over previous
#include <cuda_runtime.h>
#include <math.h>
#include <stdint.h>

// Problem dims (fixed by the dataset)
#define TT 8192
#define DD 1024
#define HH 4096
#define EE 8

// GEMM tiling
#define BM 128
#define BN 128
#define BK 16
#define TM 8
#define TN 8
#define ROWF 144   // smem row stride in floats (576B); fits 16 tiles w/ 4-float pad per 4 tiles

// ---------------- scratch (static device globals; no allocations) ----------
__device__ int   g_count[EE];
__device__ int   g_cursor[EE];
__device__ int   g_offset[EE];
__device__ int   g_sel[TT * 2];
__device__ float g_wt[TT * 2];
__device__ int   g_btok[TT * 2];
__device__ float g_bw[TT * 2];
__device__ int   g_pos[TT * 2];
__device__ float g_h[(size_t)TT * 2 * HH];
__device__ float g_yb[(size_t)TT * 2 * DD];

// ---------------- f32x2 helpers ----------------------------------------------
__device__ __forceinline__ void fma2(unsigned long long& d, unsigned long long a,
                                     unsigned long long b) {
    asm("fma.rn.f32x2 %0, %1, %2, %0;" : "+l"(d) : "l"(a), "l"(b));
}
__device__ __forceinline__ unsigned long long splat2(float a) {
    unsigned long long d;
    asm("mov.b64 %0, {%1, %1};" : "=l"(d) : "f"(a));
    return d;
}
__device__ __forceinline__ float2 unpack2(unsigned long long v) {
    float2 r;
    asm("mov.b64 {%0, %1}, %2;" : "=f"(r.x), "=f"(r.y) : "l"(v));
    return r;
}

// B smem float-offset for an 8-float tile p (0..15).
// off(p) = p*8 + (p>>2)*4  -> pads 4 floats after every 4 tiles; NO overlaps.
// Bank check: tiles 0..7 start at bytes {0,32,64,96,144,176,208,240} -> bank
// quads {0,8,16,24,4,12,20,28} (+0..3): all distinct. Tiles 8..15 likewise.
__device__ __forceinline__ int bskew(int p) { return p * 8 + (p >> 2) * 4; }

// ---------------- kernels ---------------------------------------------------

__global__ void k_zero() {
    if (threadIdx.x < EE) g_count[threadIdx.x] = 0;
}

__global__ void k_router(const float* __restrict__ x, const float* __restrict__ Wg,
                         float* __restrict__ out_logits) {
    int t = blockIdx.x * (blockDim.x >> 5) + (threadIdx.x >> 5);
    int lane = threadIdx.x & 31;
    if (t >= TT) return;
    const float* xr = x + (size_t)t * DD;

    float acc[EE];
#pragma unroll
    for (int e = 0; e < EE; e++) acc[e] = 0.f;
    for (int j = lane; j < DD; j += 32) {
        float xv = xr[j];
#pragma unroll
        for (int e = 0; e < EE; e++) acc[e] = fmaf(xv, Wg[e * DD + j], acc[e]);
    }
#pragma unroll
    for (int e = 0; e < EE; e++) {
#pragma unroll
        for (int o = 16; o > 0; o >>= 1) acc[e] += __shfl_xor_sync(0xffffffffu, acc[e], o);
    }
    if (lane == 0) {
        float mx = acc[0];
#pragma unroll
        for (int e = 1; e < EE; e++) mx = fmaxf(mx, acc[e]);
        float p[EE];
        float den = 0.f;
#pragma unroll
        for (int e = 0; e < EE; e++) { p[e] = expf(acc[e] - mx); den += p[e]; }
        float inv = 1.f / den;
#pragma unroll
        for (int e = 0; e < EE; e++) p[e] *= inv;

        int i0 = 0;
#pragma unroll
        for (int e = 1; e < EE; e++) if (p[e] > p[i0]) i0 = e;
        int i1 = (i0 == 0) ? 1 : 0;
#pragma unroll
        for (int e = 0; e < EE; e++) if (e != i0 && p[e] > p[i1]) i1 = e;

        float w0 = p[i0], w1 = p[i1];
        float s = 1.f / (w0 + w1);
        w0 *= s; w1 *= s;

        g_sel[t * 2] = i0; g_sel[t * 2 + 1] = i1;
        g_wt[t * 2] = w0;  g_wt[t * 2 + 1] = w1;
        atomicAdd(&g_count[i0], 1);
        atomicAdd(&g_count[i1], 1);
#pragma unroll
        for (int e = 0; e < EE; e++) out_logits[(size_t)t * EE + e] = acc[e];
    }
}

__global__ void k_offsets() {
    int o = 0;
    for (int e = 0; e < EE; e++) { g_offset[e] = o; g_cursor[e] = o; o += g_count[e]; }
}

__global__ void k_scatter() {
    int t = blockIdx.x * blockDim.x + threadIdx.x;
    if (t >= TT) return;
#pragma unroll
    for (int k = 0; k < 2; k++) {
        int e = g_sel[t * 2 + k];
        int idx = atomicAdd(&g_cursor[e], 1);
        g_btok[idx] = t;
        g_bw[idx] = g_wt[t * 2 + k];
        g_pos[t * 2 + k] = idx;
    }
}

// Grouped GEMM (fp32, packed f32x2 FMA, conflict-free smem).
// UP=true:  g_h[idx]  = gelu(x[gather] @ W1[e]) * gate
// UP=false: g_yb[idx] = g_h[idx] @ W2[e]
template<int KD, int ND, bool UP>
__global__ __launch_bounds__(256, 2)
void k_ggemm(const float* __restrict__ Ag, const float* __restrict__ Bg) {
    const int e = blockIdx.z;
    const int cnt = g_count[e];
    const int rt = blockIdx.y;
    if (rt * BM >= cnt) return;
    const int off = g_offset[e];
    const int n0 = blockIdx.x * BN;
    const int tid = threadIdx.x;

    __shared__ float As[2][BK][ROWF];
    __shared__ float Bs[2][BK][ROWF];
    __shared__ int   stok[BM];

    if (UP) {
        if (tid < BM) {
            int gr = rt * BM + tid;
            stok[tid] = g_btok[off + ((gr < cnt) ? gr : (cnt - 1))];
        }
    }
    __syncthreads();

    const float* Bexp = Bg + (size_t)e * KD * ND;

    // global-load slots
    const int ar0 = tid >> 2, ak4 = tid & 3;
    const int ar1 = ar0 + 64;
    const float* a_src0;
    const float* a_src1;
    if (UP) {
        a_src0 = Ag + (size_t)stok[ar0] * KD + ak4 * 4;
        a_src1 = Ag + (size_t)stok[ar1] * KD + ak4 * 4;
    } else {
        int g0 = rt * BM + ar0; if (g0 >= cnt) g0 = cnt - 1;
        int g1 = rt * BM + ar1; if (g1 >= cnt) g1 = cnt - 1;
        a_src0 = g_h + (size_t)(off + g0) * KD + ak4 * 4;
        a_src1 = g_h + (size_t)(off + g1) * KD + ak4 * 4;
    }
    const int bkk0 = tid >> 5, bn4 = tid & 31;
    const float* b_src0 = Bexp + (size_t)bkk0 * ND + n0 + bn4 * 4;
    const float* b_src1 = b_src0 + (size_t)8 * ND;
    // skewed store offset for this thread's float4 within a Bs row
    const int bso = bskew(bn4 >> 1) + (bn4 & 1) * 4;

    float4 pa0, pa1, pb0, pb1;

    auto fetch = [&](int kt) {
        pa0 = *(const float4*)(a_src0 + kt);
        pa1 = *(const float4*)(a_src1 + kt);
        pb0 = *(const float4*)(b_src0 + (size_t)kt * ND);
        pb1 = *(const float4*)(b_src1 + (size_t)kt * ND);
    };
    auto store = [&](int buf) {
        As[buf][ak4 * 4 + 0][ar0] = pa0.x;
        As[buf][ak4 * 4 + 1][ar0] = pa0.y;
        As[buf][ak4 * 4 + 2][ar0] = pa0.z;
        As[buf][ak4 * 4 + 3][ar0] = pa0.w;
        As[buf][ak4 * 4 + 0][ar1] = pa1.x;
        As[buf][ak4 * 4 + 1][ar1] = pa1.y;
        As[buf][ak4 * 4 + 2][ar1] = pa1.z;
        As[buf][ak4 * 4 + 3][ar1] = pa1.w;
        *(float4*)&Bs[buf][bkk0][bso]     = pb0;
        *(float4*)&Bs[buf][bkk0 + 8][bso] = pb1;
    };

    unsigned long long acc2[TM][TN / 2];
#pragma unroll
    for (int i = 0; i < TM; i++)
#pragma unroll
        for (int j = 0; j < TN / 2; j++) acc2[i][j] = 0ull;

    fetch(0);
    store(0);
    __syncthreads();

    // lane mapping: warp 4(M)x2(N); lane 4(M)x8(N)
    const int lane = tid & 31, wid = tid >> 5;
    const int wm = wid & 3, wn = wid >> 2;
    const int my = lane >> 3, nx = lane & 7;
    const int arow = wm * 32 + my * 8;          // thread's first M row in tile
    const int bofs = bskew(wn * 8 + nx);        // thread's skewed B float offset

    const int NK = KD / BK;
    for (int kt = 0; kt < NK; kt++) {
        const int cur = kt & 1;
        if (kt + 1 < NK) fetch((kt + 1) * BK);
#pragma unroll
        for (int k = 0; k < BK; k++) {
            float4 a03 = *(const float4*)&As[cur][k][arow];
            float4 a47 = *(const float4*)&As[cur][k][arow + 4];
            ulonglong2 b01 = *(const ulonglong2*)&Bs[cur][k][bofs];
            ulonglong2 b23 = *(const ulonglong2*)&Bs[cur][k][bofs + 4];
            unsigned long long bp0 = b01.x, bp1 = b01.y, bp2 = b23.x, bp3 = b23.y;
            float av[TM] = {a03.x, a03.y, a03.z, a03.w, a47.x, a47.y, a47.z, a47.w};
#pragma unroll
            for (int i = 0; i < TM; i++) {
                unsigned long long asp = splat2(av[i]);
                fma2(acc2[i][0], asp, bp0);
                fma2(acc2[i][1], asp, bp1);
                fma2(acc2[i][2], asp, bp2);
                fma2(acc2[i][3], asp, bp3);
            }
        }
        if (kt + 1 < NK) store(cur ^ 1);
        __syncthreads();
    }

    // epilogue: thread owns rows arow..arow+7, cols wn*64+nx*8..+8
    const int cc = wn * 64 + nx * 8;
#pragma unroll
    for (int i = 0; i < TM; i++) {
        int gr = rt * BM + arow + i;
        if (gr >= cnt) continue;
        float* crow;
        float gate = 1.f;
        if (UP) {
            gate = g_bw[off + gr];
            crow = g_h + (size_t)(off + gr) * ND;
        } else {
            crow = g_yb + (size_t)(off + gr) * ND;
        }
#pragma unroll
        for (int j2 = 0; j2 < TN / 2; j2 += 2) {
            float2 v0 = unpack2(acc2[i][j2]);
            float2 v1 = unpack2(acc2[i][j2 + 1]);
            float vv[4] = {v0.x, v0.y, v1.x, v1.y};
            if (UP) {
#pragma unroll
                for (int q = 0; q < 4; q++) {
                    float z = vv[q];
                    vv[q] = 0.5f * z * (1.f + erff(z * 0.70710678118654752f)) * gate;
                }
            }
            *(float4*)(crow + n0 + cc + j2 * 2) = make_float4(vv[0], vv[1], vv[2], vv[3]);
        }
    }
}

__global__ void k_combine(float* __restrict__ y) {
    int i = blockIdx.x * blockDim.x + threadIdx.x;
    const int nv = TT * DD / 4;
    if (i >= nv) return;
    int t = i / (DD / 4);
    int d4 = i % (DD / 4);
    int p0 = g_pos[2 * t], p1 = g_pos[2 * t + 1];
    float4 a = ((const float4*)(g_yb + (size_t)p0 * DD))[d4];
    float4 b = ((const float4*)(g_yb + (size_t)p1 * DD))[d4];
    float4 o = make_float4(a.x + b.x, a.y + b.y, a.z + b.z, a.w + b.w);
    ((float4*)(y + (size_t)t * DD))[d4] = o;
}

// ---------------- launch -----------------------------------------------------

extern "C" void kernel_launch(void* const* d_in, const int* in_sizes, int n_in,
                              void* d_out, int out_size) {
    const float* x  = (const float*)d_in[0];
    const float* Wg = (const float*)d_in[1];
    const float* W1 = (const float*)d_in[2];
    const float* W2 = (const float*)d_in[3];
    float* out = (float*)d_out;
    float* y = out;                                 // [T, D]
    float* logits = out + (size_t)TT * DD;          // [T, E]

    k_zero<<<1, 32>>>();
    k_router<<<TT / 8, 256>>>(x, Wg, logits);
    k_offsets<<<1, 1>>>();
    k_scatter<<<TT / 256, 256>>>();

    dim3 gup(HH / BN, TT / BM, EE);
    k_ggemm<DD, HH, true><<<gup, 256>>>(x, W1);

    dim3 gdn(DD / BN, TT / BM, EE);
    k_ggemm<HH, DD, false><<<gdn, 256>>>(nullptr, W2);

    k_combine<<<(TT * DD / 4 + 255) / 256, 256>>>(y);
}